// round 1
// baseline (speedup 1.0000x reference)
#include <cuda_runtime.h>
#include <stdint.h>
#include <math.h>

#define D_MODEL 1024
#define T_SEQ   2048
#define BATCH   2
#define NROWS   (BATCH * T_SEQ)      // 4096
#define DFF     4096
#define NHEADS  16
#define HDIM    64

// ---------------- scratch (device globals; no allocs allowed) ----------------
__device__ __align__(16) float g_h   [NROWS * D_MODEL];
__device__ __align__(16) float g_qkv [NROWS * 3 * D_MODEL];
__device__ __align__(16) float g_attn[NROWS * D_MODEL];
__device__ __align__(16) float g_x1  [NROWS * D_MODEL];
__device__ __align__(16) float g_h2  [NROWS * D_MODEL];
__device__ __align__(16) float g_ff  [NROWS * DFF];

// ---------------- helpers ----------------
__device__ __forceinline__ float to_tf32(float f) {
    uint32_t u;
    asm("cvt.rna.tf32.f32 %0, %1;" : "=r"(u) : "f"(f));
    return __uint_as_float(u);
}

// m16n8k8 tf32 mma, row.col, fp32 accum.
__device__ __forceinline__ void mma_tf32(float* d,
                                         float a0, float a1, float a2, float a3,
                                         float b0, float b1) {
    asm volatile(
        "mma.sync.aligned.m16n8k8.row.col.f32.tf32.tf32.f32 "
        "{%0,%1,%2,%3}, {%4,%5,%6,%7}, {%8,%9}, {%0,%1,%2,%3};\n"
        : "+f"(d[0]), "+f"(d[1]), "+f"(d[2]), "+f"(d[3])
        : "r"(__float_as_uint(a0)), "r"(__float_as_uint(a1)),
          "r"(__float_as_uint(a2)), "r"(__float_as_uint(a3)),
          "r"(__float_as_uint(b0)), "r"(__float_as_uint(b1)));
}

// ---------------- layernorm ----------------
__global__ void ln_kernel(const float* __restrict__ x,
                          const float* __restrict__ g,
                          const float* __restrict__ b,
                          float* __restrict__ out) {
    const int row = blockIdx.x;
    const int tid = threadIdx.x;
    const float4 v = reinterpret_cast<const float4*>(x + (size_t)row * D_MODEL)[tid];
    float s  = v.x + v.y + v.z + v.w;
    float sq = v.x*v.x + v.y*v.y + v.z*v.z + v.w*v.w;

    __shared__ float rs[256];
    __shared__ float rq[256];
    rs[tid] = s; rq[tid] = sq;
    __syncthreads();
    #pragma unroll
    for (int st = 128; st > 0; st >>= 1) {
        if (tid < st) { rs[tid] += rs[tid + st]; rq[tid] += rq[tid + st]; }
        __syncthreads();
    }
    const float mean = rs[0] * (1.0f / D_MODEL);
    const float var  = rq[0] * (1.0f / D_MODEL) - mean * mean;
    const float rstd = rsqrtf(var + 1e-5f);

    const float4 gv = reinterpret_cast<const float4*>(g)[tid];
    const float4 bv = reinterpret_cast<const float4*>(b)[tid];
    float4 o;
    o.x = (v.x - mean) * rstd * gv.x + bv.x;
    o.y = (v.y - mean) * rstd * gv.y + bv.y;
    o.z = (v.z - mean) * rstd * gv.z + bv.z;
    o.w = (v.w - mean) * rstd * gv.w + bv.w;
    reinterpret_cast<float4*>(out + (size_t)row * D_MODEL)[tid] = o;
}

// ---------------- generic tf32 GEMM: C = A[MxK] * B[KxN] (+bias, +epi) ----------------
// EPI: 0 = bias; 1 = bias + exact GELU; 2 = bias + residual add
#define BM 128
#define BN 128
#define BK 32
#define AS_STRIDE 36   // conflict-free A frag reads
#define BS_STRIDE 136  // conflict-free-ish B frag reads

template<int EPI>
__global__ void __launch_bounds__(256)
gemm_tf32_kernel(const float* __restrict__ A, const float* __restrict__ B,
                 const float* __restrict__ bias, const float* __restrict__ res,
                 float* __restrict__ C, int M, int N, int K) {
    __shared__ float As[BM * AS_STRIDE];
    __shared__ float Bs[BK * BS_STRIDE];

    const int tid    = threadIdx.x;
    const int lane   = tid & 31;
    const int warp   = tid >> 5;
    const int warp_m = warp >> 1;   // 0..3  (32 rows each)
    const int warp_n = warp & 1;    // 0..1  (64 cols each)
    const int bm = blockIdx.y * BM;
    const int bn = blockIdx.x * BN;

    const int lg = lane >> 2;  // group id 0..7
    const int lt = lane & 3;   // thread in group 0..3

    float c[2][8][4];
    #pragma unroll
    for (int i = 0; i < 2; i++)
        #pragma unroll
        for (int j = 0; j < 8; j++)
            #pragma unroll
            for (int k = 0; k < 4; k++) c[i][j][k] = 0.0f;

    for (int k0 = 0; k0 < K; k0 += BK) {
        // load A tile 128x32 (row-major)
        #pragma unroll
        for (int p = 0; p < 4; p++) {
            const int row = p * 32 + (tid >> 3);
            const int col = (tid & 7) * 4;
            const float4 v = *reinterpret_cast<const float4*>(
                &A[(size_t)(bm + row) * K + k0 + col]);
            As[row * AS_STRIDE + col + 0] = to_tf32(v.x);
            As[row * AS_STRIDE + col + 1] = to_tf32(v.y);
            As[row * AS_STRIDE + col + 2] = to_tf32(v.z);
            As[row * AS_STRIDE + col + 3] = to_tf32(v.w);
        }
        // load B tile 32x128 (row-major)
        #pragma unroll
        for (int p = 0; p < 4; p++) {
            const int row = p * 8 + (tid >> 5);
            const int col = (tid & 31) * 4;
            const float4 v = *reinterpret_cast<const float4*>(
                &B[(size_t)(k0 + row) * N + bn + col]);
            Bs[row * BS_STRIDE + col + 0] = to_tf32(v.x);
            Bs[row * BS_STRIDE + col + 1] = to_tf32(v.y);
            Bs[row * BS_STRIDE + col + 2] = to_tf32(v.z);
            Bs[row * BS_STRIDE + col + 3] = to_tf32(v.w);
        }
        __syncthreads();

        #pragma unroll
        for (int ks = 0; ks < 4; ks++) {
            float af[2][4];
            #pragma unroll
            for (int mi = 0; mi < 2; mi++) {
                const int m = warp_m * 32 + mi * 16 + lg;
                const int k = ks * 8 + lt;
                af[mi][0] = As[m * AS_STRIDE + k];
                af[mi][1] = As[(m + 8) * AS_STRIDE + k];
                af[mi][2] = As[m * AS_STRIDE + k + 4];
                af[mi][3] = As[(m + 8) * AS_STRIDE + k + 4];
            }
            float bf[8][2];
            #pragma unroll
            for (int nt = 0; nt < 8; nt++) {
                const int n = warp_n * 64 + nt * 8 + lg;
                const int k = ks * 8 + lt;
                bf[nt][0] = Bs[k * BS_STRIDE + n];
                bf[nt][1] = Bs[(k + 4) * BS_STRIDE + n];
            }
            #pragma unroll
            for (int mi = 0; mi < 2; mi++)
                #pragma unroll
                for (int nt = 0; nt < 8; nt++)
                    mma_tf32(c[mi][nt], af[mi][0], af[mi][1], af[mi][2], af[mi][3],
                             bf[nt][0], bf[nt][1]);
        }
        __syncthreads();
    }

    // epilogue
    #pragma unroll
    for (int mi = 0; mi < 2; mi++) {
        #pragma unroll
        for (int nt = 0; nt < 8; nt++) {
            const int col = bn + warp_n * 64 + nt * 8 + 2 * lt;
            const float b0 = bias[col], b1 = bias[col + 1];
            #pragma unroll
            for (int half = 0; half < 2; half++) {
                const int row = bm + warp_m * 32 + mi * 16 + lg + half * 8;
                float v0 = c[mi][nt][half * 2 + 0] + b0;
                float v1 = c[mi][nt][half * 2 + 1] + b1;
                if (EPI == 1) {
                    v0 = 0.5f * v0 * (1.0f + erff(v0 * 0.70710678118654752f));
                    v1 = 0.5f * v1 * (1.0f + erff(v1 * 0.70710678118654752f));
                } else if (EPI == 2) {
                    v0 += res[(size_t)row * N + col];
                    v1 += res[(size_t)row * N + col + 1];
                }
                float2 o; o.x = v0; o.y = v1;
                *reinterpret_cast<float2*>(&C[(size_t)row * N + col]) = o;
            }
        }
    }
}

// ---------------- causal flash attention (tf32 mma) ----------------
// qkv: [NROWS, 3*D_MODEL], Q at col h*64, K at 1024 + h*64, V at 2048 + h*64
// out: [NROWS, D_MODEL] at col h*64
#define ATT_STRIDE 68

__global__ void __launch_bounds__(128)
attn_kernel(const float* __restrict__ qkv, float* __restrict__ out) {
    __shared__ float Ks[64 * ATT_STRIDE];   // K tile, then reused for P tile
    __shared__ float Vs[64 * ATT_STRIDE];   // Q staging, then V tiles

    const int tid  = threadIdx.x;
    const int lane = tid & 31;
    const int warp = tid >> 5;          // 0..3, each owns 16 q rows
    const int lg = lane >> 2;
    const int lt = lane & 3;

    const int qb = blockIdx.x;          // q tile (64 rows) within batch
    const int bh = blockIdx.y;
    const int b  = bh >> 4;
    const int h  = bh & 15;

    const int q0 = qb * 64;
    const size_t rowbase = (size_t)b * T_SEQ;

    // ---- stage Q (scaled by 1/8, exact in tf32) and load frags to regs ----
    #pragma unroll
    for (int p = 0; p < 8; p++) {
        const int r = p * 8 + (tid >> 4);
        const int cc = (tid & 15) * 4;
        const float4 v = *reinterpret_cast<const float4*>(
            &qkv[(rowbase + q0 + r) * 3 * D_MODEL + h * HDIM + cc]);
        Vs[r * ATT_STRIDE + cc + 0] = to_tf32(v.x * 0.125f);
        Vs[r * ATT_STRIDE + cc + 1] = to_tf32(v.y * 0.125f);
        Vs[r * ATT_STRIDE + cc + 2] = to_tf32(v.z * 0.125f);
        Vs[r * ATT_STRIDE + cc + 3] = to_tf32(v.w * 0.125f);
    }
    __syncthreads();

    float qa[8][4];
    #pragma unroll
    for (int kt = 0; kt < 8; kt++) {
        const int m = warp * 16 + lg;
        const int k = kt * 8 + lt;
        qa[kt][0] = Vs[m * ATT_STRIDE + k];
        qa[kt][1] = Vs[(m + 8) * ATT_STRIDE + k];
        qa[kt][2] = Vs[m * ATT_STRIDE + k + 4];
        qa[kt][3] = Vs[(m + 8) * ATT_STRIDE + k + 4];
    }
    __syncthreads();

    float o[8][4];
    #pragma unroll
    for (int i = 0; i < 8; i++)
        #pragma unroll
        for (int j = 0; j < 4; j++) o[i][j] = 0.0f;
    float m0 = -INFINITY, m1 = -INFINITY;
    float l0 = 0.0f, l1 = 0.0f;

    for (int kb = 0; kb <= qb; kb++) {
        // ---- load K, V tiles (tf32) ----
        #pragma unroll
        for (int p = 0; p < 8; p++) {
            const int r = p * 8 + (tid >> 4);
            const int cc = (tid & 15) * 4;
            const size_t grow = (rowbase + kb * 64 + r) * (size_t)(3 * D_MODEL);
            const float4 kv = *reinterpret_cast<const float4*>(
                &qkv[grow + D_MODEL + h * HDIM + cc]);
            const float4 vv = *reinterpret_cast<const float4*>(
                &qkv[grow + 2 * D_MODEL + h * HDIM + cc]);
            Ks[r * ATT_STRIDE + cc + 0] = to_tf32(kv.x);
            Ks[r * ATT_STRIDE + cc + 1] = to_tf32(kv.y);
            Ks[r * ATT_STRIDE + cc + 2] = to_tf32(kv.z);
            Ks[r * ATT_STRIDE + cc + 3] = to_tf32(kv.w);
            Vs[r * ATT_STRIDE + cc + 0] = to_tf32(vv.x);
            Vs[r * ATT_STRIDE + cc + 1] = to_tf32(vv.y);
            Vs[r * ATT_STRIDE + cc + 2] = to_tf32(vv.z);
            Vs[r * ATT_STRIDE + cc + 3] = to_tf32(vv.w);
        }
        __syncthreads();

        // ---- S = Q K^T (already scaled) ----
        float s[8][4];
        #pragma unroll
        for (int i = 0; i < 8; i++)
            #pragma unroll
            for (int j = 0; j < 4; j++) s[i][j] = 0.0f;
        #pragma unroll
        for (int kt = 0; kt < 8; kt++) {
            const int k = kt * 8 + lt;
            #pragma unroll
            for (int nt = 0; nt < 8; nt++) {
                const int n = nt * 8 + lg;   // t index within tile
                const float bb0 = Ks[n * ATT_STRIDE + k];
                const float bb1 = Ks[n * ATT_STRIDE + k + 4];
                mma_tf32(s[nt], qa[kt][0], qa[kt][1], qa[kt][2], qa[kt][3], bb0, bb1);
            }
        }

        // ---- causal mask on diagonal block ----
        if (kb == qb) {
            #pragma unroll
            for (int nt = 0; nt < 8; nt++) {
                #pragma unroll
                for (int j = 0; j < 4; j++) {
                    const int trow = warp * 16 + lg + (j >= 2 ? 8 : 0);
                    const int tcol = nt * 8 + 2 * lt + (j & 1);
                    if (tcol > trow) s[nt][j] = -INFINITY;
                }
            }
        }

        // ---- online softmax ----
        float mx0 = -INFINITY, mx1 = -INFINITY;
        #pragma unroll
        for (int nt = 0; nt < 8; nt++) {
            mx0 = fmaxf(mx0, fmaxf(s[nt][0], s[nt][1]));
            mx1 = fmaxf(mx1, fmaxf(s[nt][2], s[nt][3]));
        }
        mx0 = fmaxf(mx0, __shfl_xor_sync(0xffffffff, mx0, 1));
        mx0 = fmaxf(mx0, __shfl_xor_sync(0xffffffff, mx0, 2));
        mx1 = fmaxf(mx1, __shfl_xor_sync(0xffffffff, mx1, 1));
        mx1 = fmaxf(mx1, __shfl_xor_sync(0xffffffff, mx1, 2));
        const float mn0 = fmaxf(m0, mx0);
        const float mn1 = fmaxf(m1, mx1);

        float sum0 = 0.0f, sum1 = 0.0f;
        #pragma unroll
        for (int nt = 0; nt < 8; nt++) {
            s[nt][0] = __expf(s[nt][0] - mn0);
            s[nt][1] = __expf(s[nt][1] - mn0);
            s[nt][2] = __expf(s[nt][2] - mn1);
            s[nt][3] = __expf(s[nt][3] - mn1);
            sum0 += s[nt][0] + s[nt][1];
            sum1 += s[nt][2] + s[nt][3];
        }
        sum0 += __shfl_xor_sync(0xffffffff, sum0, 1);
        sum0 += __shfl_xor_sync(0xffffffff, sum0, 2);
        sum1 += __shfl_xor_sync(0xffffffff, sum1, 1);
        sum1 += __shfl_xor_sync(0xffffffff, sum1, 2);

        const float a0 = __expf(m0 - mn0);
        const float a1 = __expf(m1 - mn1);
        l0 = l0 * a0 + sum0;
        l1 = l1 * a1 + sum1;
        m0 = mn0; m1 = mn1;
        #pragma unroll
        for (int nt = 0; nt < 8; nt++) {
            o[nt][0] *= a0; o[nt][1] *= a0;
            o[nt][2] *= a1; o[nt][3] *= a1;
        }

        // ---- write P (tf32) into Ks buffer ----
        __syncthreads();   // everyone done reading Ks
        #pragma unroll
        for (int nt = 0; nt < 8; nt++) {
            const int r0 = warp * 16 + lg;
            const int tc = nt * 8 + 2 * lt;
            Ks[r0 * ATT_STRIDE + tc]       = to_tf32(s[nt][0]);
            Ks[r0 * ATT_STRIDE + tc + 1]   = to_tf32(s[nt][1]);
            Ks[(r0+8) * ATT_STRIDE + tc]   = to_tf32(s[nt][2]);
            Ks[(r0+8) * ATT_STRIDE + tc+1] = to_tf32(s[nt][3]);
        }
        __syncthreads();

        // ---- O += P @ V ----
        #pragma unroll
        for (int kt = 0; kt < 8; kt++) {
            const int m = warp * 16 + lg;
            const int k = kt * 8 + lt;
            const float pa0 = Ks[m * ATT_STRIDE + k];
            const float pa1 = Ks[(m + 8) * ATT_STRIDE + k];
            const float pa2 = Ks[m * ATT_STRIDE + k + 4];
            const float pa3 = Ks[(m + 8) * ATT_STRIDE + k + 4];
            #pragma unroll
            for (int nt = 0; nt < 8; nt++) {
                const int n = nt * 8 + lg;   // d index
                const float bb0 = Vs[k * ATT_STRIDE + n];
                const float bb1 = Vs[(k + 4) * ATT_STRIDE + n];
                mma_tf32(o[nt], pa0, pa1, pa2, pa3, bb0, bb1);
            }
        }
        __syncthreads();   // before next K/V load overwrites tiles
    }

    // ---- normalize and write out ----
    const float inv0 = 1.0f / l0;
    const float inv1 = 1.0f / l1;
    #pragma unroll
    for (int nt = 0; nt < 8; nt++) {
        const int dcol = h * HDIM + nt * 8 + 2 * lt;
        const int r0 = q0 + warp * 16 + lg;
        float2 w0; w0.x = o[nt][0] * inv0; w0.y = o[nt][1] * inv0;
        float2 w1; w1.x = o[nt][2] * inv1; w1.y = o[nt][3] * inv1;
        *reinterpret_cast<float2*>(&out[(rowbase + r0) * D_MODEL + dcol])     = w0;
        *reinterpret_cast<float2*>(&out[(rowbase + r0 + 8) * D_MODEL + dcol]) = w1;
    }
}

// ---------------- launch ----------------
extern "C" void kernel_launch(void* const* d_in, const int* in_sizes, int n_in,
                              void* d_out, int out_size) {
    const float* x      = (const float*)d_in[0];
    const float* ln1_g  = (const float*)d_in[1];
    const float* ln1_b  = (const float*)d_in[2];
    const float* qkv_w  = (const float*)d_in[3];
    const float* qkv_b  = (const float*)d_in[4];
    const float* proj_w = (const float*)d_in[5];
    const float* proj_b = (const float*)d_in[6];
    const float* ln2_g  = (const float*)d_in[7];
    const float* ln2_b  = (const float*)d_in[8];
    const float* mlp_w1 = (const float*)d_in[9];
    const float* mlp_b1 = (const float*)d_in[10];
    const float* mlp_w2 = (const float*)d_in[11];
    const float* mlp_b2 = (const float*)d_in[12];
    float* out = (float*)d_out;

    float *h, *qkv, *attn, *x1, *h2, *ff;
    cudaGetSymbolAddress((void**)&h,    g_h);
    cudaGetSymbolAddress((void**)&qkv,  g_qkv);
    cudaGetSymbolAddress((void**)&attn, g_attn);
    cudaGetSymbolAddress((void**)&x1,   g_x1);
    cudaGetSymbolAddress((void**)&h2,   g_h2);
    cudaGetSymbolAddress((void**)&ff,   g_ff);

    // 1. LN1
    ln_kernel<<<NROWS, 256>>>(x, ln1_g, ln1_b, h);
    // 2. QKV = h @ qkv_w + qkv_b
    gemm_tf32_kernel<0><<<dim3(3 * D_MODEL / BN, NROWS / BM), 256>>>(
        h, qkv_w, qkv_b, nullptr, qkv, NROWS, 3 * D_MODEL, D_MODEL);
    // 3. causal attention
    attn_kernel<<<dim3(T_SEQ / 64, BATCH * NHEADS), 128>>>(qkv, attn);
    // 4. x1 = x + attn @ proj_w + proj_b
    gemm_tf32_kernel<2><<<dim3(D_MODEL / BN, NROWS / BM), 256>>>(
        attn, proj_w, proj_b, x, x1, NROWS, D_MODEL, D_MODEL);
    // 5. LN2
    ln_kernel<<<NROWS, 256>>>(x1, ln2_g, ln2_b, h2);
    // 6. ff = gelu(h2 @ mlp_w1 + mlp_b1)
    gemm_tf32_kernel<1><<<dim3(DFF / BN, NROWS / BM), 256>>>(
        h2, mlp_w1, mlp_b1, nullptr, ff, NROWS, DFF, D_MODEL);
    // 7. out = x1 + ff @ mlp_w2 + mlp_b2
    gemm_tf32_kernel<2><<<dim3(D_MODEL / BN, NROWS / BM), 256>>>(
        ff, mlp_w2, mlp_b2, x1, out, NROWS, D_MODEL, DFF);
}

// round 2
// speedup vs baseline: 1.1943x; 1.1943x over previous
#include <cuda_runtime.h>
#include <stdint.h>
#include <math.h>

#define D_MODEL 1024
#define T_SEQ   2048
#define BATCH   2
#define NROWS   (BATCH * T_SEQ)
#define DFF     4096
#define NHEADS  16
#define HDIM    64

// ---------------- scratch ----------------
__device__ __align__(16) float g_h   [NROWS * D_MODEL];
__device__ __align__(16) float g_qkv [NROWS * 3 * D_MODEL];
__device__ __align__(16) float g_attn[NROWS * D_MODEL];
__device__ __align__(16) float g_x1  [NROWS * D_MODEL];
__device__ __align__(16) float g_h2  [NROWS * D_MODEL];
__device__ __align__(16) float g_ff  [NROWS * DFF];

// ---------------- helpers ----------------
__device__ __forceinline__ float to_tf32(float f) {
    uint32_t u;
    asm("cvt.rna.tf32.f32 %0, %1;" : "=r"(u) : "f"(f));
    return __uint_as_float(u);
}

__device__ __forceinline__ void mma_tf32(float* d,
                                         float a0, float a1, float a2, float a3,
                                         float b0, float b1) {
    asm volatile(
        "mma.sync.aligned.m16n8k8.row.col.f32.tf32.tf32.f32 "
        "{%0,%1,%2,%3}, {%4,%5,%6,%7}, {%8,%9}, {%0,%1,%2,%3};\n"
        : "+f"(d[0]), "+f"(d[1]), "+f"(d[2]), "+f"(d[3])
        : "r"(__float_as_uint(a0)), "r"(__float_as_uint(a1)),
          "r"(__float_as_uint(a2)), "r"(__float_as_uint(a3)),
          "r"(__float_as_uint(b0)), "r"(__float_as_uint(b1)));
}

__device__ __forceinline__ void cp16(uint32_t s, const float* g) {
    asm volatile("cp.async.cg.shared.global [%0], [%1], 16;\n" :: "r"(s), "l"(g));
}
__device__ __forceinline__ void cp_commit() {
    asm volatile("cp.async.commit_group;\n");
}
__device__ __forceinline__ void cp_wait1() {
    asm volatile("cp.async.wait_group 1;\n");
}
__device__ __forceinline__ void cp_wait0() {
    asm volatile("cp.async.wait_group 0;\n");
}

// ---------------- layernorm ----------------
__global__ void ln_kernel(const float* __restrict__ x,
                          const float* __restrict__ g,
                          const float* __restrict__ b,
                          float* __restrict__ out) {
    const int row = blockIdx.x;
    const int tid = threadIdx.x;
    const float4 v = reinterpret_cast<const float4*>(x + (size_t)row * D_MODEL)[tid];
    float s  = v.x + v.y + v.z + v.w;
    float sq = v.x*v.x + v.y*v.y + v.z*v.z + v.w*v.w;

    __shared__ float rs[256];
    __shared__ float rq[256];
    rs[tid] = s; rq[tid] = sq;
    __syncthreads();
    #pragma unroll
    for (int st = 128; st > 0; st >>= 1) {
        if (tid < st) { rs[tid] += rs[tid + st]; rq[tid] += rq[tid + st]; }
        __syncthreads();
    }
    const float mean = rs[0] * (1.0f / D_MODEL);
    const float var  = rq[0] * (1.0f / D_MODEL) - mean * mean;
    const float rstd = rsqrtf(var + 1e-5f);

    const float4 gv = reinterpret_cast<const float4*>(g)[tid];
    const float4 bv = reinterpret_cast<const float4*>(b)[tid];
    float4 o;
    o.x = (v.x - mean) * rstd * gv.x + bv.x;
    o.y = (v.y - mean) * rstd * gv.y + bv.y;
    o.z = (v.z - mean) * rstd * gv.z + bv.z;
    o.w = (v.w - mean) * rstd * gv.w + bv.w;
    reinterpret_cast<float4*>(out + (size_t)row * D_MODEL)[tid] = o;
}

// ---------------- tf32 GEMM, cp.async double-buffered ----------------
// EPI: 0 = bias; 1 = bias + exact GELU; 2 = bias + residual add
#define BM 128
#define BN 128
#define BK 32
#define AS_STRIDE 36
#define BS_STRIDE 136
#define A_TILE (BM * AS_STRIDE)   // 4608 floats
#define B_TILE (BK * BS_STRIDE)   // 4352 floats
#define GEMM_SMEM ((A_TILE + B_TILE) * 2 * 4)   // 71680 bytes

template<int EPI>
__global__ void __launch_bounds__(256, 2)
gemm_tf32_kernel(const float* __restrict__ A, const float* __restrict__ B,
                 const float* __restrict__ bias, const float* __restrict__ res,
                 float* __restrict__ C, int M, int N, int K) {
    extern __shared__ float sm[];
    // layout: As[0], As[1], Bs[0], Bs[1]
    const uint32_t smem_u32 = (uint32_t)__cvta_generic_to_shared(sm);

    const int tid    = threadIdx.x;
    const int lane   = tid & 31;
    const int warp   = tid >> 5;
    const int warp_m = warp >> 1;
    const int warp_n = warp & 1;
    const int bm = blockIdx.y * BM;
    const int bn = blockIdx.x * BN;
    const int lg = lane >> 2;
    const int lt = lane & 3;

    float c[2][8][4];
    #pragma unroll
    for (int i = 0; i < 2; i++)
        #pragma unroll
        for (int j = 0; j < 8; j++)
            #pragma unroll
            for (int k = 0; k < 4; k++) c[i][j][k] = 0.0f;

    // per-thread load coords
    const int a_row = tid >> 3;         // +i*32
    const int a_col = (tid & 7) * 4;
    const int b_row = tid >> 5;         // +i*8
    const int b_col = (tid & 31) * 4;

    const int KT = K / BK;

    auto load_tile = [&](int k0, int st) {
        const uint32_t abase = smem_u32 + st * A_TILE * 4;
        const uint32_t bbase = smem_u32 + (2 * A_TILE + st * B_TILE) * 4;
        #pragma unroll
        for (int i = 0; i < 4; i++) {
            const int row = a_row + i * 32;
            cp16(abase + (row * AS_STRIDE + a_col) * 4,
                 &A[(size_t)(bm + row) * K + k0 + a_col]);
        }
        #pragma unroll
        for (int i = 0; i < 4; i++) {
            const int row = b_row + i * 8;
            cp16(bbase + (row * BS_STRIDE + b_col) * 4,
                 &B[(size_t)(k0 + row) * N + bn + b_col]);
        }
        cp_commit();
    };

    load_tile(0, 0);

    for (int kt = 0; kt < KT; kt++) {
        const int st = kt & 1;
        if (kt + 1 < KT) { load_tile((kt + 1) * BK, st ^ 1); cp_wait1(); }
        else             { cp_wait0(); }
        __syncthreads();

        const float* As = sm + st * A_TILE;
        const float* Bs = sm + 2 * A_TILE + st * B_TILE;

        #pragma unroll
        for (int ks = 0; ks < 4; ks++) {
            float af[2][4];
            #pragma unroll
            for (int mi = 0; mi < 2; mi++) {
                const int m = warp_m * 32 + mi * 16 + lg;
                const int k = ks * 8 + lt;
                af[mi][0] = As[m * AS_STRIDE + k];
                af[mi][1] = As[(m + 8) * AS_STRIDE + k];
                af[mi][2] = As[m * AS_STRIDE + k + 4];
                af[mi][3] = As[(m + 8) * AS_STRIDE + k + 4];
            }
            float bf[8][2];
            #pragma unroll
            for (int nt = 0; nt < 8; nt++) {
                const int n = warp_n * 64 + nt * 8 + lg;
                const int k = ks * 8 + lt;
                bf[nt][0] = Bs[k * BS_STRIDE + n];
                bf[nt][1] = Bs[(k + 4) * BS_STRIDE + n];
            }
            #pragma unroll
            for (int mi = 0; mi < 2; mi++)
                #pragma unroll
                for (int nt = 0; nt < 8; nt++)
                    mma_tf32(c[mi][nt], af[mi][0], af[mi][1], af[mi][2], af[mi][3],
                             bf[nt][0], bf[nt][1]);
        }
        __syncthreads();
    }

    // epilogue
    #pragma unroll
    for (int mi = 0; mi < 2; mi++) {
        #pragma unroll
        for (int nt = 0; nt < 8; nt++) {
            const int col = bn + warp_n * 64 + nt * 8 + 2 * lt;
            const float b0 = bias[col], b1 = bias[col + 1];
            #pragma unroll
            for (int half = 0; half < 2; half++) {
                const int row = bm + warp_m * 32 + mi * 16 + lg + half * 8;
                float v0 = c[mi][nt][half * 2 + 0] + b0;
                float v1 = c[mi][nt][half * 2 + 1] + b1;
                if (EPI == 1) {
                    v0 = 0.5f * v0 * (1.0f + erff(v0 * 0.70710678118654752f));
                    v1 = 0.5f * v1 * (1.0f + erff(v1 * 0.70710678118654752f));
                } else if (EPI == 2) {
                    v0 += res[(size_t)row * N + col];
                    v1 += res[(size_t)row * N + col + 1];
                }
                float2 o; o.x = v0; o.y = v1;
                *reinterpret_cast<float2*>(&C[(size_t)row * N + col]) = o;
            }
        }
    }
}

// ---------------- causal flash attention v2 ----------------
// 256 threads, 128 q-rows/block, 64-wide K/V tiles, cp.async double-buffered,
// P kept in registers via shuffle repack.
#define AST 72
#define ATT_TILE (64 * AST)          // 4608 floats
#define ATT_SMEM (4 * ATT_TILE * 4)  // 73728 bytes

__global__ void __launch_bounds__(256, 2)
attn_kernel(const float* __restrict__ qkv, float* __restrict__ out) {
    extern __shared__ float sm[];
    // Ks[0], Ks[1], Vs[0], Vs[1], each ATT_TILE floats
    const uint32_t smem_u32 = (uint32_t)__cvta_generic_to_shared(sm);

    const int tid  = threadIdx.x;
    const int lane = tid & 31;
    const int warp = tid >> 5;          // 0..7, each 16 q-rows
    const int lg = lane >> 2;
    const int lt = lane & 3;

    const int qb = gridDim.x - 1 - blockIdx.x;  // heavy tiles first
    const int bh = blockIdx.y;
    const int b  = bh >> 4;
    const int h  = bh & 15;
    const int q0 = qb * 128;
    const size_t rowbase = (size_t)b * T_SEQ;

    // ---- stage Q (scaled, rna-cvt) into sm[0 .. 128*AST) ----
    #pragma unroll
    for (int p = 0; p < 8; p++) {
        const int r = p * 16 + (tid >> 4);
        const int cc = (tid & 15) * 4;
        const float4 v = *reinterpret_cast<const float4*>(
            &qkv[(rowbase + q0 + r) * (size_t)(3 * D_MODEL) + h * HDIM + cc]);
        float4 o;
        o.x = to_tf32(v.x * 0.125f);
        o.y = to_tf32(v.y * 0.125f);
        o.z = to_tf32(v.z * 0.125f);
        o.w = to_tf32(v.w * 0.125f);
        *reinterpret_cast<float4*>(&sm[r * AST + cc]) = o;
    }
    __syncthreads();

    float qa[8][4];
    #pragma unroll
    for (int kt = 0; kt < 8; kt++) {
        const int m = warp * 16 + lg;
        const int k = kt * 8 + lt;
        qa[kt][0] = sm[m * AST + k];
        qa[kt][1] = sm[(m + 8) * AST + k];
        qa[kt][2] = sm[m * AST + k + 4];
        qa[kt][3] = sm[(m + 8) * AST + k + 4];
    }
    __syncthreads();

    // per-thread cp.async coords: K/V tile = 64 rows x 64 floats = 1024 chunks each
    const int kv_r = tid >> 4;         // +i*16
    const int kv_c = (tid & 15) * 4;

    auto prefetch = [&](int kb, int st) {
        const float* base = &qkv[(rowbase + (size_t)kb * 64) * (3 * D_MODEL) + h * HDIM];
        const uint32_t kb32 = smem_u32 + st * ATT_TILE * 4;
        const uint32_t vb32 = smem_u32 + (2 + st) * ATT_TILE * 4;
        #pragma unroll
        for (int i = 0; i < 4; i++) {
            const int r = kv_r + i * 16;
            cp16(kb32 + (r * AST + kv_c) * 4, base + (size_t)r * (3 * D_MODEL) + D_MODEL     + kv_c);
            cp16(vb32 + (r * AST + kv_c) * 4, base + (size_t)r * (3 * D_MODEL) + 2 * D_MODEL + kv_c);
        }
        cp_commit();
    };

    float o[8][4];
    #pragma unroll
    for (int i = 0; i < 8; i++)
        #pragma unroll
        for (int j = 0; j < 4; j++) o[i][j] = 0.0f;
    float m0 = -INFINITY, m1 = -INFINITY;
    float l0 = 0.0f, l1 = 0.0f;

    const int nkb = 2 * qb + 2;
    prefetch(0, 0);

    for (int kb = 0; kb < nkb; kb++) {
        const int st = kb & 1;
        if (kb + 1 < nkb) { prefetch(kb + 1, st ^ 1); cp_wait1(); }
        else              { cp_wait0(); }
        __syncthreads();

        const float* Ks = sm + st * ATT_TILE;
        const float* Vs = sm + (2 + st) * ATT_TILE;

        // ---- S = Q K^T ----
        float s[8][4];
        #pragma unroll
        for (int i = 0; i < 8; i++)
            #pragma unroll
            for (int j = 0; j < 4; j++) s[i][j] = 0.0f;
        #pragma unroll
        for (int kt = 0; kt < 8; kt++) {
            const int k = kt * 8 + lt;
            #pragma unroll
            for (int nt = 0; nt < 8; nt++) {
                const int n = nt * 8 + lg;
                const float bb0 = Ks[n * AST + k];
                const float bb1 = Ks[n * AST + k + 4];
                mma_tf32(s[nt], qa[kt][0], qa[kt][1], qa[kt][2], qa[kt][3], bb0, bb1);
            }
        }

        // ---- causal mask (only on diagonal tiles) ----
        const int t0 = kb * 64;
        if (t0 + 63 > q0 + warp * 16) {
            #pragma unroll
            for (int nt = 0; nt < 8; nt++) {
                #pragma unroll
                for (int j = 0; j < 4; j++) {
                    const int trow = q0 + warp * 16 + lg + (j >= 2 ? 8 : 0);
                    const int tcol = t0 + nt * 8 + 2 * lt + (j & 1);
                    if (tcol > trow) s[nt][j] = -INFINITY;
                }
            }
        }

        // ---- online softmax ----
        float mx0 = -INFINITY, mx1 = -INFINITY;
        #pragma unroll
        for (int nt = 0; nt < 8; nt++) {
            mx0 = fmaxf(mx0, fmaxf(s[nt][0], s[nt][1]));
            mx1 = fmaxf(mx1, fmaxf(s[nt][2], s[nt][3]));
        }
        mx0 = fmaxf(mx0, __shfl_xor_sync(0xffffffff, mx0, 1));
        mx0 = fmaxf(mx0, __shfl_xor_sync(0xffffffff, mx0, 2));
        mx1 = fmaxf(mx1, __shfl_xor_sync(0xffffffff, mx1, 1));
        mx1 = fmaxf(mx1, __shfl_xor_sync(0xffffffff, mx1, 2));
        const float mn0 = fmaxf(m0, mx0);
        const float mn1 = fmaxf(m1, mx1);

        float sum0 = 0.0f, sum1 = 0.0f;
        #pragma unroll
        for (int nt = 0; nt < 8; nt++) {
            s[nt][0] = __expf(s[nt][0] - mn0);
            s[nt][1] = __expf(s[nt][1] - mn0);
            s[nt][2] = __expf(s[nt][2] - mn1);
            s[nt][3] = __expf(s[nt][3] - mn1);
            sum0 += s[nt][0] + s[nt][1];
            sum1 += s[nt][2] + s[nt][3];
        }
        sum0 += __shfl_xor_sync(0xffffffff, sum0, 1);
        sum0 += __shfl_xor_sync(0xffffffff, sum0, 2);
        sum1 += __shfl_xor_sync(0xffffffff, sum1, 1);
        sum1 += __shfl_xor_sync(0xffffffff, sum1, 2);

        const float a0 = __expf(m0 - mn0);
        const float a1 = __expf(m1 - mn1);
        l0 = l0 * a0 + sum0;
        l1 = l1 * a1 + sum1;
        m0 = mn0; m1 = mn1;
        #pragma unroll
        for (int nt = 0; nt < 8; nt++) {
            o[nt][0] *= a0; o[nt][1] *= a0;
            o[nt][2] *= a1; o[nt][3] *= a1;
        }

        // ---- O += P @ V : repack P c-layout -> a-layout via shuffles ----
        const int srcA = lg * 4 + (lt >> 1);
        const int srcB = srcA + 2;
        const bool odd = (lt & 1);
        #pragma unroll
        for (int kt = 0; kt < 8; kt++) {
            // P block columns kt*8..kt*8+7 become k-dim of PV mma
            float x0 = __shfl_sync(0xffffffff, s[kt][0], srcA);
            float x1 = __shfl_sync(0xffffffff, s[kt][1], srcA);
            float y0 = __shfl_sync(0xffffffff, s[kt][2], srcA);
            float y1 = __shfl_sync(0xffffffff, s[kt][3], srcA);
            float z0 = __shfl_sync(0xffffffff, s[kt][0], srcB);
            float z1 = __shfl_sync(0xffffffff, s[kt][1], srcB);
            float w0 = __shfl_sync(0xffffffff, s[kt][2], srcB);
            float w1 = __shfl_sync(0xffffffff, s[kt][3], srcB);
            const float pa0 = to_tf32(odd ? x1 : x0);
            const float pa1 = to_tf32(odd ? y1 : y0);
            const float pa2 = to_tf32(odd ? z1 : z0);
            const float pa3 = to_tf32(odd ? w1 : w0);

            const int k = kt * 8 + lt;
            #pragma unroll
            for (int nt = 0; nt < 8; nt++) {
                const int n = nt * 8 + lg;
                const float bb0 = Vs[k * AST + n];
                const float bb1 = Vs[(k + 4) * AST + n];
                mma_tf32(o[nt], pa0, pa1, pa2, pa3, bb0, bb1);
            }
        }
        __syncthreads();
    }

    // ---- normalize + write ----
    const float inv0 = 1.0f / l0;
    const float inv1 = 1.0f / l1;
    #pragma unroll
    for (int nt = 0; nt < 8; nt++) {
        const int dcol = h * HDIM + nt * 8 + 2 * lt;
        const size_t r0 = rowbase + q0 + warp * 16 + lg;
        float2 w0; w0.x = o[nt][0] * inv0; w0.y = o[nt][1] * inv0;
        float2 w1; w1.x = o[nt][2] * inv1; w1.y = o[nt][3] * inv1;
        *reinterpret_cast<float2*>(&out[r0 * D_MODEL + dcol])       = w0;
        *reinterpret_cast<float2*>(&out[(r0 + 8) * D_MODEL + dcol]) = w1;
    }
}

// ---------------- launch ----------------
extern "C" void kernel_launch(void* const* d_in, const int* in_sizes, int n_in,
                              void* d_out, int out_size) {
    const float* x      = (const float*)d_in[0];
    const float* ln1_g  = (const float*)d_in[1];
    const float* ln1_b  = (const float*)d_in[2];
    const float* qkv_w  = (const float*)d_in[3];
    const float* qkv_b  = (const float*)d_in[4];
    const float* proj_w = (const float*)d_in[5];
    const float* proj_b = (const float*)d_in[6];
    const float* ln2_g  = (const float*)d_in[7];
    const float* ln2_b  = (const float*)d_in[8];
    const float* mlp_w1 = (const float*)d_in[9];
    const float* mlp_b1 = (const float*)d_in[10];
    const float* mlp_w2 = (const float*)d_in[11];
    const float* mlp_b2 = (const float*)d_in[12];
    float* out = (float*)d_out;

    float *h, *qkv, *attn, *x1, *h2, *ff;
    cudaGetSymbolAddress((void**)&h,    g_h);
    cudaGetSymbolAddress((void**)&qkv,  g_qkv);
    cudaGetSymbolAddress((void**)&attn, g_attn);
    cudaGetSymbolAddress((void**)&x1,   g_x1);
    cudaGetSymbolAddress((void**)&h2,   g_h2);
    cudaGetSymbolAddress((void**)&ff,   g_ff);

    cudaFuncSetAttribute(gemm_tf32_kernel<0>, cudaFuncAttributeMaxDynamicSharedMemorySize, GEMM_SMEM);
    cudaFuncSetAttribute(gemm_tf32_kernel<1>, cudaFuncAttributeMaxDynamicSharedMemorySize, GEMM_SMEM);
    cudaFuncSetAttribute(gemm_tf32_kernel<2>, cudaFuncAttributeMaxDynamicSharedMemorySize, GEMM_SMEM);
    cudaFuncSetAttribute(attn_kernel,         cudaFuncAttributeMaxDynamicSharedMemorySize, ATT_SMEM);

    // 1. LN1
    ln_kernel<<<NROWS, 256>>>(x, ln1_g, ln1_b, h);
    // 2. QKV
    gemm_tf32_kernel<0><<<dim3(3 * D_MODEL / BN, NROWS / BM), 256, GEMM_SMEM>>>(
        h, qkv_w, qkv_b, nullptr, qkv, NROWS, 3 * D_MODEL, D_MODEL);
    // 3. attention (128 q-rows per block)
    attn_kernel<<<dim3(T_SEQ / 128, BATCH * NHEADS), 256, ATT_SMEM>>>(qkv, attn);
    // 4. x1 = x + attn @ proj_w + proj_b
    gemm_tf32_kernel<2><<<dim3(D_MODEL / BN, NROWS / BM), 256, GEMM_SMEM>>>(
        attn, proj_w, proj_b, x, x1, NROWS, D_MODEL, D_MODEL);
    // 5. LN2
    ln_kernel<<<NROWS, 256>>>(x1, ln2_g, ln2_b, h2);
    // 6. ff = gelu(h2 @ mlp_w1 + mlp_b1)
    gemm_tf32_kernel<1><<<dim3(DFF / BN, NROWS / BM), 256, GEMM_SMEM>>>(
        h2, mlp_w1, mlp_b1, nullptr, ff, NROWS, DFF, D_MODEL);
    // 7. out = x1 + ff @ mlp_w2 + mlp_b2
    gemm_tf32_kernel<2><<<dim3(D_MODEL / BN, NROWS / BM), 256, GEMM_SMEM>>>(
        ff, mlp_w2, mlp_b2, x1, out, NROWS, D_MODEL, DFF);
}